// round 14
// baseline (speedup 1.0000x reference)
#include <cuda_runtime.h>

#define IMG_H 1024
#define IMG_W 1024
#define STRIP_W 128      // per-warp strip width (32 lanes x float4)
#define STRIP_H 32       // per-warp strip height (output rows)
#define WARPS   4        // warps per block, each an independent y-strip
#define PF_DIST 8        // L2 prefetch distance in rows

struct Raw { float4 v; float l2, l1, r0, r1; };

__device__ __forceinline__ int reflect_idx(int g, int n) {
    g = (g < 0) ? -g : g;
    g = (g >= n) ? (2 * n - 2 - g) : g;
    return g;
}

// Pure memory phase: vector load + predicated edge scalars.
__device__ __forceinline__ Raw load_raw(const float* __restrict__ row, int xb,
                                        int lane, int xl2, int xl1,
                                        int xr0, int xr1) {
    Raw t;
    t.v = *reinterpret_cast<const float4*>(row + xb);
    if (lane == 0)  { t.l2 = row[xl2]; t.l1 = row[xl1]; }
    if (lane == 31) { t.r0 = row[xr0]; t.r1 = row[xr1]; }
    return t;
}

// Pure compute phase: shuffles + adds, no memory.
__device__ __forceinline__ float4 hsum_from(const Raw& t, int lane) {
    const float4 v = t.v;
    float lz = __shfl_up_sync(0xFFFFFFFFu, v.z, 1);   // e[x-2]
    float lw = __shfl_up_sync(0xFFFFFFFFu, v.w, 1);   // e[x-1]
    float rx = __shfl_down_sync(0xFFFFFFFFu, v.x, 1); // e[x+4]
    float ry = __shfl_down_sync(0xFFFFFFFFu, v.y, 1); // e[x+5]
    if (lane == 0)  { lz = t.l2; lw = t.l1; }
    if (lane == 31) { rx = t.r0; ry = t.r1; }
    const float c  = v.y + v.z;
    const float s4 = v.x + c + v.w;
    float4 h;
    h.x = lz + lw + v.x + c;
    h.y = lw + s4;
    h.z = s4 + rx;
    h.w = c + v.w + rx + ry;
    return h;
}

__global__ __launch_bounds__(32 * WARPS, 9)
void box5_kernel(const float* __restrict__ in, float* __restrict__ out) {
    const int lane  = threadIdx.x;
    const int plane = blockIdx.z;
    const float* __restrict__ p = in  + (size_t)plane * IMG_H * IMG_W;
    float* __restrict__       o = out + (size_t)plane * IMG_H * IMG_W;

    const int xt = blockIdx.x * STRIP_W;
    const int xb = xt + lane * 4;
    const int y0 = (blockIdx.y * WARPS + threadIdx.y) * STRIP_H;

    const int xl2 = reflect_idx(xt - 2, IMG_W);
    const int xl1 = reflect_idx(xt - 1, IMG_W);
    const int xr0 = reflect_idx(xt + STRIP_W,     IMG_W);
    const int xr1 = reflect_idx(xt + STRIP_W + 1, IMG_W);

    const bool pf_lane = ((lane & 7) == 0);   // lanes 0,8,16,24 cover 4x128B lines

    #define ROWP(gy) (p + (size_t)(gy) * IMG_W)
    #define PF(gy) do { if (pf_lane) { \
        const float* _a = ROWP(gy) + xb; \
        asm volatile("prefetch.global.L2 [%0];" :: "l"(_a)); } } while (0)

    // Prefetch the first chunk of the strip into L2 up-front.
    #pragma unroll
    for (int k = 4; k < PF_DIST + 4; ++k) PF(y0 + k);

    // Prime: batch 6 independent row loads (y0-2 .. y0+3) before any compute.
    const int gyA = reflect_idx(y0 - 2, IMG_H);
    const int gyB = reflect_idx(y0 - 1, IMG_H);
    Raw ra  = load_raw(ROWP(gyA),    xb, lane, xl2, xl1, xr0, xr1);
    Raw rb  = load_raw(ROWP(gyB),    xb, lane, xl2, xl1, xr0, xr1);
    Raw rc  = load_raw(ROWP(y0),     xb, lane, xl2, xl1, xr0, xr1);
    Raw rd  = load_raw(ROWP(y0 + 1), xb, lane, xl2, xl1, xr0, xr1);
    Raw cur = load_raw(ROWP(y0 + 2), xb, lane, xl2, xl1, xr0, xr1);
    Raw nxt = load_raw(ROWP(y0 + 3), xb, lane, xl2, xl1, xr0, xr1);

    float4 h0 = hsum_from(ra, lane);
    float4 h1 = hsum_from(rb, lane);
    float4 h2 = hsum_from(rc, lane);
    float4 h3 = hsum_from(rd, lane);

    float4 vs;
    vs.x = h0.x + h1.x + h2.x + h3.x;
    vs.y = h0.y + h1.y + h2.y + h3.y;
    vs.z = h0.z + h1.z + h2.z + h3.z;
    vs.w = h0.w + h1.w + h2.w + h3.w;

    const float inv25 = 1.0f / 25.0f;

    #pragma unroll 4
    for (int r = 0; r < STRIP_H; ++r) {
        // Stream prefetch: PF_DIST rows ahead (no regs, no scoreboard).
        PF(reflect_idx(y0 + r + 4 + PF_DIST, IMG_H));

        // Load 2 rows ahead of use; mostly L2 hits thanks to the prefetch.
        const int gyF = reflect_idx(y0 + r + 4, IMG_H);
        Raw fut = load_raw(ROWP(gyF), xb, lane, xl2, xl1, xr0, xr1);

        const float4 h4 = hsum_from(cur, lane);

        float4 ov;
        ov.x = (vs.x + h4.x) * inv25;
        ov.y = (vs.y + h4.y) * inv25;
        ov.z = (vs.z + h4.z) * inv25;
        ov.w = (vs.w + h4.w) * inv25;
        __stcs(reinterpret_cast<float4*>(o + (size_t)(y0 + r) * IMG_W + xb), ov);

        vs.x += h4.x - h0.x;
        vs.y += h4.y - h0.y;
        vs.z += h4.z - h0.z;
        vs.w += h4.w - h0.w;
        h0 = h1; h1 = h2; h2 = h3; h3 = h4;
        cur = nxt; nxt = fut;
    }
    #undef PF
    #undef ROWP
}

extern "C" void kernel_launch(void* const* d_in, const int* in_sizes, int n_in,
                              void* d_out, int out_size) {
    const float* image = (const float*)d_in[0];
    float* out = (float*)d_out;

    const int planes = in_sizes[0] / (IMG_H * IMG_W);   // 48

    dim3 block(32, WARPS);                               // 128 threads
    dim3 grid(IMG_W / STRIP_W,                           // 8
              IMG_H / (STRIP_H * WARPS),                 // 8
              planes);                                   // 48
    box5_kernel<<<grid, block>>>(image, out);
}

// round 15
// speedup vs baseline: 1.0096x; 1.0096x over previous
#include <cuda_runtime.h>

#define IMG_H 1024
#define IMG_W 1024
#define STRIP_W 128      // per-warp strip width (32 lanes x float4)
#define STRIP_H 32       // per-warp strip height (output rows)
#define WARPS   4        // warps per block, each an independent y-strip

// Edge scalars share 2 regs: lane 0 keeps (x-2, x-1), lane 31 keeps (x+4, x+5).
struct Raw { float4 v; float fa, fb; };

__device__ __forceinline__ int reflect_idx(int g, int n) {
    g = (g < 0) ? -g : g;
    g = (g >= n) ? (2 * n - 2 - g) : g;
    return g;
}

__device__ __forceinline__ Raw load_raw(const float* __restrict__ row, int xb,
                                        int lane, int xl2, int xl1,
                                        int xr0, int xr1) {
    Raw t;
    t.v = *reinterpret_cast<const float4*>(row + xb);
    if (lane == 0)       { t.fa = row[xl2]; t.fb = row[xl1]; }
    else if (lane == 31) { t.fa = row[xr0]; t.fb = row[xr1]; }
    return t;
}

__device__ __forceinline__ float4 hsum_from(const Raw& t, int lane) {
    const float4 v = t.v;
    float lz = __shfl_up_sync(0xFFFFFFFFu, v.z, 1);   // e[x-2]
    float lw = __shfl_up_sync(0xFFFFFFFFu, v.w, 1);   // e[x-1]
    float rx = __shfl_down_sync(0xFFFFFFFFu, v.x, 1); // e[x+4]
    float ry = __shfl_down_sync(0xFFFFFFFFu, v.y, 1); // e[x+5]
    if (lane == 0)  { lz = t.fa; lw = t.fb; }
    if (lane == 31) { rx = t.fa; ry = t.fb; }
    const float c  = v.y + v.z;
    const float s4 = v.x + c + v.w;
    float4 h;
    h.x = lz + lw + v.x + c;
    h.y = lw + s4;
    h.z = s4 + rx;
    h.w = c + v.w + rx + ry;
    return h;
}

__global__ __launch_bounds__(32 * WARPS, 8)
void box5_kernel(const float* __restrict__ in, float* __restrict__ out) {
    const int lane  = threadIdx.x;
    const int plane = blockIdx.z;
    const float* __restrict__ p = in  + (size_t)plane * IMG_H * IMG_W;
    float* __restrict__       o = out + (size_t)plane * IMG_H * IMG_W;

    const int xt = blockIdx.x * STRIP_W;
    const int xb = xt + lane * 4;
    const int y0 = (blockIdx.y * WARPS + threadIdx.y) * STRIP_H;

    const int xl2 = reflect_idx(xt - 2, IMG_W);
    const int xl1 = reflect_idx(xt - 1, IMG_W);
    const int xr0 = reflect_idx(xt + STRIP_W,     IMG_W);
    const int xr1 = reflect_idx(xt + STRIP_W + 1, IMG_W);

    #define ROWP(gy) (p + (size_t)(gy) * IMG_W)

    // Prologue: 8 independent row loads (y0-2 .. y0+5) batched up-front.
    const int gyA = reflect_idx(y0 - 2, IMG_H);
    const int gyB = reflect_idx(y0 - 1, IMG_H);
    Raw ra = load_raw(ROWP(gyA),    xb, lane, xl2, xl1, xr0, xr1);
    Raw rb = load_raw(ROWP(gyB),    xb, lane, xl2, xl1, xr0, xr1);
    Raw rc = load_raw(ROWP(y0),     xb, lane, xl2, xl1, xr0, xr1);
    Raw rd = load_raw(ROWP(y0 + 1), xb, lane, xl2, xl1, xr0, xr1);
    Raw cur = load_raw(ROWP(y0 + 2), xb, lane, xl2, xl1, xr0, xr1);
    Raw n1  = load_raw(ROWP(y0 + 3), xb, lane, xl2, xl1, xr0, xr1);
    Raw n2  = load_raw(ROWP(y0 + 4), xb, lane, xl2, xl1, xr0, xr1);
    Raw n3  = load_raw(ROWP(y0 + 5), xb, lane, xl2, xl1, xr0, xr1);

    float4 h0 = hsum_from(ra, lane);
    float4 h1 = hsum_from(rb, lane);
    float4 h2 = hsum_from(rc, lane);
    float4 h3 = hsum_from(rd, lane);

    float4 vs;
    vs.x = h0.x + h1.x + h2.x + h3.x;
    vs.y = h0.y + h1.y + h2.y + h3.y;
    vs.z = h0.z + h1.z + h2.z + h3.z;
    vs.w = h0.w + h1.w + h2.w + h3.w;

    const float inv25 = 1.0f / 25.0f;

    #pragma unroll 4
    for (int r = 0; r < STRIP_H; ++r) {
        // Demand-load 4 rows ahead of use (consumed at iteration r+4):
        // keeps 4-5 independent LDG.128s outstanding per warp.
        const int gyF = reflect_idx(y0 + r + 6, IMG_H);
        Raw fut = load_raw(ROWP(gyF), xb, lane, xl2, xl1, xr0, xr1);

        const float4 h4 = hsum_from(cur, lane);

        float4 ov;
        ov.x = (vs.x + h4.x) * inv25;
        ov.y = (vs.y + h4.y) * inv25;
        ov.z = (vs.z + h4.z) * inv25;
        ov.w = (vs.w + h4.w) * inv25;
        __stcs(reinterpret_cast<float4*>(o + (size_t)(y0 + r) * IMG_W + xb), ov);

        vs.x += h4.x - h0.x;
        vs.y += h4.y - h0.y;
        vs.z += h4.z - h0.z;
        vs.w += h4.w - h0.w;
        h0 = h1; h1 = h2; h2 = h3; h3 = h4;
        cur = n1; n1 = n2; n2 = n3; n3 = fut;
    }
    #undef ROWP
}

extern "C" void kernel_launch(void* const* d_in, const int* in_sizes, int n_in,
                              void* d_out, int out_size) {
    const float* image = (const float*)d_in[0];
    float* out = (float*)d_out;

    const int planes = in_sizes[0] / (IMG_H * IMG_W);   // 48

    dim3 block(32, WARPS);                               // 128 threads
    dim3 grid(IMG_W / STRIP_W,                           // 8
              IMG_H / (STRIP_H * WARPS),                 // 8
              planes);                                   // 48
    box5_kernel<<<grid, block>>>(image, out);
}